// round 3
// baseline (speedup 1.0000x reference)
#include <cuda_runtime.h>
#include <cuda_bf16.h>
#include <cstddef>

// Problem constants
#define NTOK   65536          // B*S = 8*8192
#define DMODEL 512
#define HID    2048
#define NEXP   8
#define CHUNK  4096           // tokens per expert slice -> expert = (row>>12)&7

typedef unsigned long long ull;

// ---------------- scratch (static device globals; no allocation) ------------
__device__ float g_norm [(size_t)NTOK * DMODEL];           // 134 MB
__device__ float g_xattn[(size_t)NTOK * DMODEL];           // 134 MB
__device__ float g_h    [(size_t)NTOK * HID];              // 536 MB
__device__ float g_y    [(size_t)NTOK * DMODEL];           // 134 MB

// ---------------- helpers ---------------------------------------------------
__device__ __forceinline__ ull dup2(float v) {
    ull r; asm("mov.b64 %0, {%1, %1};" : "=l"(r) : "f"(v)); return r;
}
__device__ __forceinline__ void fma2(ull& d, ull a, ull b) {
    asm("fma.rn.f32x2 %0, %1, %2, %0;" : "+l"(d) : "l"(a), "l"(b));
}
__device__ __forceinline__ float2 unpack2(ull v) {
    float2 f; asm("mov.b64 {%0, %1}, %2;" : "=f"(f.x), "=f"(f.y) : "l"(v)); return f;
}
__device__ __forceinline__ float gelu_erf(float x) {
    return 0.5f * x * (1.0f + erff(x * 0.70710678118654752f));
}

// ---------------- LayerNorm (warp per token) --------------------------------
__global__ void __launch_bounds__(256) ln_kernel(
    const float* __restrict__ x, const float* __restrict__ g,
    const float* __restrict__ b, float* __restrict__ out)
{
    const int warp = threadIdx.x >> 5;
    const int lane = threadIdx.x & 31;
    const int token = blockIdx.x * 8 + warp;
    const float* row = x + (size_t)token * DMODEL;

    float4 v[4];
    float s = 0.f, ss = 0.f;
#pragma unroll
    for (int q = 0; q < 4; q++) {
        v[q] = *(const float4*)(row + (size_t)(q * 32 + lane) * 4);
        s  += v[q].x + v[q].y + v[q].z + v[q].w;
        ss  = fmaf(v[q].x, v[q].x, ss);
        ss  = fmaf(v[q].y, v[q].y, ss);
        ss  = fmaf(v[q].z, v[q].z, ss);
        ss  = fmaf(v[q].w, v[q].w, ss);
    }
#pragma unroll
    for (int off = 16; off > 0; off >>= 1) {
        s  += __shfl_xor_sync(0xffffffffu, s,  off);
        ss += __shfl_xor_sync(0xffffffffu, ss, off);
    }
    const float mu  = s * (1.0f / DMODEL);
    const float var = ss * (1.0f / DMODEL) - mu * mu;
    const float rs  = rsqrtf(var + 1e-5f);

    float* orow = out + (size_t)token * DMODEL;
#pragma unroll
    for (int q = 0; q < 4; q++) {
        const int c = (q * 32 + lane) * 4;
        float4 gg = *(const float4*)(g + c);
        float4 bb = *(const float4*)(b + c);
        float4 o;
        o.x = (v[q].x - mu) * rs * gg.x + bb.x;
        o.y = (v[q].y - mu) * rs * gg.y + bb.y;
        o.z = (v[q].z - mu) * rs * gg.z + bb.z;
        o.w = (v[q].w - mu) * rs * gg.w + bb.w;
        *(float4*)(orow + c) = o;
    }
}

// ---------------- GEMM: C[r,c] = sum_k A[r,k]*W[e][c,k] + bias (+resid)(gelu)
// BM=BN=128, BK=16, 256 threads, thread tile 8x8 via f32x2 (row-pairs x 8 cols)
template<bool GELU, bool RESID>
__global__ void __launch_bounds__(256) gemm_kernel(
    const float* __restrict__ A, const float* __restrict__ W,
    const float* __restrict__ bias, const float* __restrict__ resid,
    float* __restrict__ C, int K, int OUTD,
    size_t w_estride, int b_estride)
{
    __shared__ __align__(16) float As[16][128];
    __shared__ __align__(16) float Bs[16][128];

    const int tid  = threadIdx.x;
    const int tx   = tid & 15;
    const int ty   = tid >> 4;
    const int row0 = blockIdx.y * 128;
    const int col0 = blockIdx.x * 128;

    const int e = (row0 >> 12) & 7;          // expert id (chunk = 4096 tokens)
    const float* Wp = W + (w_estride ? (size_t)e * w_estride : 0);
    const float* Bp = bias + (b_estride ? e * b_estride : 0);

    ull acc[4][8];
#pragma unroll
    for (int p = 0; p < 4; p++)
#pragma unroll
        for (int j = 0; j < 8; j++) acc[p][j] = 0ull;

    for (int k0 = 0; k0 < K; k0 += 16) {
#pragma unroll
        for (int s = 0; s < 2; s++) {
            const int idx = tid * 2 + s;     // 0..511
            const int r   = idx >> 2;        // 0..127
            const int kk  = (idx & 3) << 2;  // 0,4,8,12
            float4 va = *(const float4*)(A  + (size_t)(row0 + r) * K + (k0 + kk));
            As[kk + 0][r] = va.x; As[kk + 1][r] = va.y;
            As[kk + 2][r] = va.z; As[kk + 3][r] = va.w;
            float4 vb = *(const float4*)(Wp + (size_t)(col0 + r) * K + (k0 + kk));
            Bs[kk + 0][r] = vb.x; Bs[kk + 1][r] = vb.y;
            Bs[kk + 2][r] = vb.z; Bs[kk + 3][r] = vb.w;
        }
        __syncthreads();
#pragma unroll
        for (int k = 0; k < 16; k++) {
            ulonglong2 a0 = *(const ulonglong2*)&As[k][ty * 4];
            ulonglong2 a1 = *(const ulonglong2*)&As[k][64 + ty * 4];
            float4 b0 = *(const float4*)&Bs[k][tx * 4];
            float4 b1 = *(const float4*)&Bs[k][64 + tx * 4];
            ull ap[4] = { a0.x, a0.y, a1.x, a1.y };
            ull bd[8] = { dup2(b0.x), dup2(b0.y), dup2(b0.z), dup2(b0.w),
                          dup2(b1.x), dup2(b1.y), dup2(b1.z), dup2(b1.w) };
#pragma unroll
            for (int p = 0; p < 4; p++)
#pragma unroll
                for (int j = 0; j < 8; j++)
                    fma2(acc[p][j], ap[p], bd[j]);
        }
        __syncthreads();
    }

    // epilogue
#pragma unroll
    for (int p = 0; p < 4; p++) {
        const int rbase = row0 + ((p < 2) ? (ty * 4 + 2 * p)
                                          : (64 + ty * 4 + 2 * (p - 2)));
        float v0[8], v1[8];
#pragma unroll
        for (int j = 0; j < 8; j++) {
            float2 u = unpack2(acc[p][j]);
            v0[j] = u.x; v1[j] = u.y;
        }
#pragma unroll
        for (int h = 0; h < 2; h++) {
            const int r = rbase + h;
            const float* vv = h ? v1 : v0;
#pragma unroll
            for (int g = 0; g < 2; g++) {
                const int c = col0 + (g == 0 ? tx * 4 : 64 + tx * 4);
                float4 bb = *(const float4*)(Bp + c);
                float4 o;
                o.x = vv[g * 4 + 0] + bb.x;
                o.y = vv[g * 4 + 1] + bb.y;
                o.z = vv[g * 4 + 2] + bb.z;
                o.w = vv[g * 4 + 3] + bb.w;
                if (RESID) {
                    float4 rr = *(const float4*)(resid + (size_t)r * OUTD + c);
                    o.x += rr.x; o.y += rr.y; o.z += rr.z; o.w += rr.w;
                }
                if (GELU) {
                    o.x = gelu_erf(o.x); o.y = gelu_erf(o.y);
                    o.z = gelu_erf(o.z); o.w = gelu_erf(o.w);
                }
                *(float4*)(C + (size_t)r * OUTD + c) = o;
            }
        }
    }
}

// ---------------- launch ----------------------------------------------------
extern "C" void kernel_launch(void* const* d_in, const int* in_sizes, int n_in,
                              void* d_out, int out_size)
{
    const float* x      = (const float*)d_in[0];
    const float* ln_g   = (const float*)d_in[1];
    const float* ln_b   = (const float*)d_in[2];
    const float* attn_w = (const float*)d_in[3];
    const float* attn_b = (const float*)d_in[4];
    /* gate_w d_in[5] unused — gating does not affect the output path */
    const float* fc1_w  = (const float*)d_in[6];
    const float* fc1_b  = (const float*)d_in[7];
    const float* fc2_w  = (const float*)d_in[8];
    const float* fc2_b  = (const float*)d_in[9];
    const float* next_w = (const float*)d_in[10];
    const float* next_b = (const float*)d_in[11];
    float* out = (float*)d_out;

    void *p_norm, *p_xattn, *p_h, *p_y;
    cudaGetSymbolAddress(&p_norm,  g_norm);
    cudaGetSymbolAddress(&p_xattn, g_xattn);
    cudaGetSymbolAddress(&p_h,     g_h);
    cudaGetSymbolAddress(&p_y,     g_y);
    float* norm  = (float*)p_norm;
    float* xattn = (float*)p_xattn;
    float* hbuf  = (float*)p_h;
    float* ybuf  = (float*)p_y;

    // 1) LayerNorm
    ln_kernel<<<NTOK / 8, 256>>>(x, ln_g, ln_b, norm);

    // 2) attn linear + residual: xattn = norm @ attn_w^T + attn_b + x
    gemm_kernel<false, true><<<dim3(DMODEL / 128, NTOK / 128), 256>>>(
        norm, attn_w, attn_b, x, xattn, DMODEL, DMODEL, 0, 0);

    // 3) fc1 + gelu (per-expert weights): h = gelu(xattn @ fc1_w[e]^T + fc1_b[e])
    gemm_kernel<true, false><<<dim3(HID / 128, NTOK / 128), 256>>>(
        xattn, fc1_w, fc1_b, nullptr, hbuf, DMODEL, HID,
        (size_t)HID * DMODEL, HID);

    // 4) fc2: y = h @ fc2_w[e]^T + fc2_b[e]
    gemm_kernel<false, false><<<dim3(DMODEL / 128, NTOK / 128), 256>>>(
        hbuf, fc2_w, fc2_b, nullptr, ybuf, HID, DMODEL,
        (size_t)DMODEL * HID, DMODEL);

    // 5) next linear + gelu: out = gelu(y @ next_w^T + next_b)
    gemm_kernel<true, false><<<dim3(DMODEL / 128, NTOK / 128), 256>>>(
        ybuf, next_w, next_b, nullptr, out, DMODEL, DMODEL, 0, 0);
}

// round 5
// speedup vs baseline: 3.2086x; 3.2086x over previous
#include <cuda_runtime.h>
#include <cstdint>
#include <cstddef>

// ---------------- problem constants -----------------------------------------
#define NTOK   65536          // B*S
#define DMODEL 512
#define HID    2048

// GEMM tiling
#define BM 128
#define BN 256
#define BK 32                 // fp32 K elements per smem stage (=128B rows)
#define THREADS 256
#define A_BYTES 16384         // 128 rows * 128B
#define B_BYTES 32768         // 256 rows * 128B
#define STG_BYTES 49152
#define SMEM_BYTES 98304      // 2 stages

// ---------------- scratch (static device globals; no allocation) ------------
__device__ float g_norm [(size_t)NTOK * DMODEL];
__device__ float g_xattn[(size_t)NTOK * DMODEL];
__device__ float g_h    [(size_t)NTOK * HID];
__device__ float g_y    [(size_t)NTOK * DMODEL];

// ---------------- PTX helpers ------------------------------------------------
__device__ __forceinline__ uint32_t smem_u32(const void* p) {
    uint32_t a;
    asm("{ .reg .u64 t; cvta.to.shared.u64 t, %1; cvt.u32.u64 %0, t; }"
        : "=r"(a) : "l"(p));
    return a;
}
__device__ __forceinline__ float to_tf32(float x) {
    float r;
    asm("cvt.rna.tf32.f32 %0, %1;" : "=f"(r) : "f"(x));
    return r;
}
__device__ __forceinline__ void ldsm4(uint32_t& r0, uint32_t& r1,
                                      uint32_t& r2, uint32_t& r3, uint32_t addr) {
    asm volatile("ldmatrix.sync.aligned.m8n8.x4.shared.b16 {%0,%1,%2,%3}, [%4];"
                 : "=r"(r0), "=r"(r1), "=r"(r2), "=r"(r3) : "r"(addr));
}
__device__ __forceinline__ void mma_tf32(float* d, const uint32_t* a,
                                         uint32_t b0, uint32_t b1) {
    asm volatile(
        "mma.sync.aligned.m16n8k8.row.col.f32.tf32.tf32.f32 "
        "{%0,%1,%2,%3}, {%4,%5,%6,%7}, {%8,%9}, {%0,%1,%2,%3};"
        : "+f"(d[0]), "+f"(d[1]), "+f"(d[2]), "+f"(d[3])
        : "r"(a[0]), "r"(a[1]), "r"(a[2]), "r"(a[3]), "r"(b0), "r"(b1));
}
__device__ __forceinline__ float gelu_erf(float x) {
    return 0.5f * x * (1.0f + erff(x * 0.70710678118654752f));
}
__device__ __forceinline__ uint32_t swz(uint32_t off) {
    return off ^ ((off >> 3) & 0x70);
}

// ---------------- LayerNorm (warp per token) --------------------------------
__global__ void __launch_bounds__(256) ln_kernel(
    const float* __restrict__ x, const float* __restrict__ g,
    const float* __restrict__ b, float* __restrict__ out)
{
    const int warp = threadIdx.x >> 5;
    const int lane = threadIdx.x & 31;
    const int token = blockIdx.x * 8 + warp;
    const float* row = x + (size_t)token * DMODEL;

    float4 v[4];
    float s = 0.f, ss = 0.f;
#pragma unroll
    for (int q = 0; q < 4; q++) {
        v[q] = *(const float4*)(row + (size_t)(q * 32 + lane) * 4);
        s  += v[q].x + v[q].y + v[q].z + v[q].w;
        ss  = fmaf(v[q].x, v[q].x, ss);
        ss  = fmaf(v[q].y, v[q].y, ss);
        ss  = fmaf(v[q].z, v[q].z, ss);
        ss  = fmaf(v[q].w, v[q].w, ss);
    }
#pragma unroll
    for (int off = 16; off > 0; off >>= 1) {
        s  += __shfl_xor_sync(0xffffffffu, s,  off);
        ss += __shfl_xor_sync(0xffffffffu, ss, off);
    }
    const float mu  = s * (1.0f / DMODEL);
    const float var = ss * (1.0f / DMODEL) - mu * mu;
    const float rs  = rsqrtf(var + 1e-5f);

    float* orow = out + (size_t)token * DMODEL;
#pragma unroll
    for (int q = 0; q < 4; q++) {
        const int c = (q * 32 + lane) * 4;
        float4 gg = *(const float4*)(g + c);
        float4 bb = *(const float4*)(b + c);
        float4 o;
        o.x = (v[q].x - mu) * rs * gg.x + bb.x;
        o.y = (v[q].y - mu) * rs * gg.y + bb.y;
        o.z = (v[q].z - mu) * rs * gg.z + bb.z;
        o.w = (v[q].w - mu) * rs * gg.w + bb.w;
        *(float4*)(orow + c) = o;
    }
}

// ---------------- tf32 mma.sync GEMM -----------------------------------------
// C[r,c] = sum_k A[r,k] * W[e][c,k] + bias[e][c] (+resid[r,c]) (gelu)
// BM=128, BN=256, BK=32; 8 warps, warp tile 64x64 (4x8 m16n8k8 frags)
template<bool GELU, bool RESID>
__global__ void __launch_bounds__(THREADS, 1)
tc_gemm(const float* __restrict__ A, const float* __restrict__ W,
        const float* __restrict__ bias, const float* __restrict__ resid,
        float* __restrict__ C, int K, int OUTD,
        size_t w_estride, int b_estride)
{
    extern __shared__ char smem[];
    const uint32_t sb = smem_u32(smem);
    const int tid  = threadIdx.x;
    const int wid  = tid >> 5;
    const int lane = tid & 31;
    const int row0 = blockIdx.y * BM;
    const int col0 = blockIdx.x * BN;

    const int e = (row0 >> 12) & 7;              // expert id (4096-token chunks)
    const float* Wp = W + (w_estride ? (size_t)e * w_estride : 0);
    const float* Bp = bias + (b_estride ? e * b_estride : 0);

    const int wm = wid & 1;                      // M half (0/1) -> 64 rows
    const int wn = wid >> 1;                     // N quarter (0..3) -> 64 cols

    // ldmatrix lane-derived offsets
    const int aRow  = (lane & 7) + ((lane >> 3) & 1) * 8;
    const int aBSel = (lane >> 4) * 16;
    const int bRow  = (lane & 7) + ((lane >> 4) & 1) * 8;
    const int bBSel = ((lane >> 3) & 1) * 16;

    // staging indices (per thread): A 4 quads, B 8 quads of float4
    const int sr = tid >> 3;                     // 0..31 base row group
    const int sq = tid & 7;                      // 16B chunk in 128B row

    float acc[4][8][4];
#pragma unroll
    for (int i = 0; i < 4; i++)
#pragma unroll
        for (int j = 0; j < 8; j++)
#pragma unroll
            for (int q = 0; q < 4; q++) acc[i][j][q] = 0.f;

    const int nst = K / BK;

    // ---- prologue: stage 0 ----
    {
        float4 va[4], vb[8];
#pragma unroll
        for (int i = 0; i < 4; i++)
            va[i] = *(const float4*)(A + (size_t)(row0 + sr + i * 32) * K + sq * 4);
#pragma unroll
        for (int i = 0; i < 8; i++)
            vb[i] = *(const float4*)(Wp + (size_t)(col0 + sr + i * 32) * K + sq * 4);
        char* ab = smem;
        char* bb = smem + A_BYTES;
#pragma unroll
        for (int i = 0; i < 4; i++) {
            float4 t; t.x = to_tf32(va[i].x); t.y = to_tf32(va[i].y);
            t.z = to_tf32(va[i].z); t.w = to_tf32(va[i].w);
            *(float4*)(ab + swz((uint32_t)((sr + i * 32) * 128 + sq * 16))) = t;
        }
#pragma unroll
        for (int i = 0; i < 8; i++) {
            float4 t; t.x = to_tf32(vb[i].x); t.y = to_tf32(vb[i].y);
            t.z = to_tf32(vb[i].z); t.w = to_tf32(vb[i].w);
            *(float4*)(bb + swz((uint32_t)((sr + i * 32) * 128 + sq * 16))) = t;
        }
    }
    __syncthreads();

    for (int s = 0; s < nst; ++s) {
        const int buf = s & 1;
        const bool next = (s + 1) < nst;
        float4 va[4], vb[8];
        if (next) {
            const int k0 = (s + 1) * BK;
#pragma unroll
            for (int i = 0; i < 4; i++)
                va[i] = *(const float4*)(A + (size_t)(row0 + sr + i * 32) * K + k0 + sq * 4);
#pragma unroll
            for (int i = 0; i < 8; i++)
                vb[i] = *(const float4*)(Wp + (size_t)(col0 + sr + i * 32) * K + k0 + sq * 4);
        }

        // ---- compute current stage ----
        const uint32_t sbA = sb + buf * STG_BYTES;
        const uint32_t sbB = sbA + A_BYTES;
#pragma unroll
        for (int kk = 0; kk < 4; ++kk) {
            uint32_t af[4][4], bf[4][4];
#pragma unroll
            for (int i = 0; i < 4; ++i) {
                uint32_t off = (uint32_t)((wm * 64 + i * 16 + aRow) * 128 + kk * 32 + aBSel);
                ldsm4(af[i][0], af[i][1], af[i][2], af[i][3], sbA + swz(off));
            }
#pragma unroll
            for (int j = 0; j < 4; ++j) {
                uint32_t off = (uint32_t)((wn * 64 + j * 16 + bRow) * 128 + kk * 32 + bBSel);
                ldsm4(bf[j][0], bf[j][1], bf[j][2], bf[j][3], sbB + swz(off));
            }
#pragma unroll
            for (int i = 0; i < 4; ++i)
#pragma unroll
                for (int j = 0; j < 4; ++j) {
                    mma_tf32(acc[i][2 * j],     af[i], bf[j][0], bf[j][1]);
                    mma_tf32(acc[i][2 * j + 1], af[i], bf[j][2], bf[j][3]);
                }
        }

        if (next) {
            char* ab = smem + (buf ^ 1) * STG_BYTES;
            char* bb = ab + A_BYTES;
#pragma unroll
            for (int i = 0; i < 4; i++) {
                float4 t; t.x = to_tf32(va[i].x); t.y = to_tf32(va[i].y);
                t.z = to_tf32(va[i].z); t.w = to_tf32(va[i].w);
                *(float4*)(ab + swz((uint32_t)((sr + i * 32) * 128 + sq * 16))) = t;
            }
#pragma unroll
            for (int i = 0; i < 8; i++) {
                float4 t; t.x = to_tf32(vb[i].x); t.y = to_tf32(vb[i].y);
                t.z = to_tf32(vb[i].z); t.w = to_tf32(vb[i].w);
                *(float4*)(bb + swz((uint32_t)((sr + i * 32) * 128 + sq * 16))) = t;
            }
            __syncthreads();
        }
    }

    // ---- epilogue: direct float2 stores --------------------------------------
    const int gr  = lane >> 2;
    const int ctg = lane & 3;
#pragma unroll
    for (int j = 0; j < 8; ++j) {
        const int col = col0 + wn * 64 + j * 8 + 2 * ctg;
        float2 bv = *(const float2*)(Bp + col);
#pragma unroll
        for (int i = 0; i < 4; ++i) {
            const int ra = row0 + wm * 64 + i * 16 + gr;
            const int rb = ra + 8;
            float2 o0, o1;
            o0.x = acc[i][j][0] + bv.x;  o0.y = acc[i][j][1] + bv.y;
            o1.x = acc[i][j][2] + bv.x;  o1.y = acc[i][j][3] + bv.y;
            if (RESID) {
                float2 r0 = *(const float2*)(resid + (size_t)ra * OUTD + col);
                float2 r1 = *(const float2*)(resid + (size_t)rb * OUTD + col);
                o0.x += r0.x; o0.y += r0.y;
                o1.x += r1.x; o1.y += r1.y;
            }
            if (GELU) {
                o0.x = gelu_erf(o0.x); o0.y = gelu_erf(o0.y);
                o1.x = gelu_erf(o1.x); o1.y = gelu_erf(o1.y);
            }
            *(float2*)(C + (size_t)ra * OUTD + col) = o0;
            *(float2*)(C + (size_t)rb * OUTD + col) = o1;
        }
    }
}

// ---------------- launch ------------------------------------------------------
extern "C" void kernel_launch(void* const* d_in, const int* in_sizes, int n_in,
                              void* d_out, int out_size)
{
    const float* x      = (const float*)d_in[0];
    const float* ln_g   = (const float*)d_in[1];
    const float* ln_b   = (const float*)d_in[2];
    const float* attn_w = (const float*)d_in[3];
    const float* attn_b = (const float*)d_in[4];
    /* gate_w d_in[5] unused — gating does not affect the output path */
    const float* fc1_w  = (const float*)d_in[6];
    const float* fc1_b  = (const float*)d_in[7];
    const float* fc2_w  = (const float*)d_in[8];
    const float* fc2_b  = (const float*)d_in[9];
    const float* next_w = (const float*)d_in[10];
    const float* next_b = (const float*)d_in[11];
    float* out = (float*)d_out;

    void *p_norm, *p_xattn, *p_h, *p_y;
    cudaGetSymbolAddress(&p_norm,  g_norm);
    cudaGetSymbolAddress(&p_xattn, g_xattn);
    cudaGetSymbolAddress(&p_h,     g_h);
    cudaGetSymbolAddress(&p_y,     g_y);
    float* norm  = (float*)p_norm;
    float* xattn = (float*)p_xattn;
    float* hbuf  = (float*)p_h;
    float* ybuf  = (float*)p_y;

    cudaFuncSetAttribute(tc_gemm<false, true>,
                         cudaFuncAttributeMaxDynamicSharedMemorySize, SMEM_BYTES);
    cudaFuncSetAttribute(tc_gemm<true, false>,
                         cudaFuncAttributeMaxDynamicSharedMemorySize, SMEM_BYTES);
    cudaFuncSetAttribute(tc_gemm<false, false>,
                         cudaFuncAttributeMaxDynamicSharedMemorySize, SMEM_BYTES);

    // 1) LayerNorm
    ln_kernel<<<NTOK / 8, 256>>>(x, ln_g, ln_b, norm);

    // 2) attn linear + residual
    tc_gemm<false, true><<<dim3(DMODEL / BN, NTOK / BM), THREADS, SMEM_BYTES>>>(
        norm, attn_w, attn_b, x, xattn, DMODEL, DMODEL, 0, 0);

    // 3) fc1 + gelu (per-expert)
    tc_gemm<true, false><<<dim3(HID / BN, NTOK / BM), THREADS, SMEM_BYTES>>>(
        xattn, fc1_w, fc1_b, nullptr, hbuf, DMODEL, HID,
        (size_t)HID * DMODEL, HID);

    // 4) fc2 (per-expert)
    tc_gemm<false, false><<<dim3(DMODEL / BN, NTOK / BM), THREADS, SMEM_BYTES>>>(
        hbuf, fc2_w, fc2_b, nullptr, ybuf, HID, DMODEL,
        (size_t)DMODEL * HID, DMODEL);

    // 5) next linear + gelu
    tc_gemm<true, false><<<dim3(DMODEL / BN, NTOK / BM), THREADS, SMEM_BYTES>>>(
        ybuf, next_w, next_b, nullptr, out, DMODEL, DMODEL, 0, 0);
}